// round 14
// baseline (speedup 1.0000x reference)
#include <cuda_runtime.h>
#include <cuda_bf16.h>
#include <cstdint>

// Problem constants (fixed shapes for TimeWindowBlock_3925600108827)
#define H    64      // hidden
#define FF   36      // MLP hidden
#define SEQ  200     // S
#define NW   8       // W windows
#define KTST 204     // kT row stride (floats): 4*204 mod 32 == 16 -> conflict-free transpose stores
#define MTST 40      // MT row stride
#define SPST 204     // score-partials row stride

typedef unsigned long long u64;

// -------- mask dtype autodetection (bool may arrive as i32 / f32 / u8) ----
__device__ int g_mask_mode;   // 0 = int32, 1 = float32, 2 = byte

__global__ void detect_mask_kernel(const unsigned int* m, int nwords) {
    __shared__ int s_not01, s_not0f;
    if (threadIdx.x == 0) { s_not01 = 0; s_not0f = 0; }
    __syncthreads();
    int n01 = 0, n0f = 0;
    for (int i = threadIdx.x; i < nwords; i += blockDim.x) {
        unsigned int w = m[i];
        if (w > 1u) n01 = 1;
        if (w != 0u && w != 0x3f800000u) n0f = 1;
    }
    if (n01) s_not01 = 1;
    if (n0f) s_not0f = 1;
    __syncthreads();
    if (threadIdx.x == 0)
        g_mask_mode = (!s_not01) ? 0 : ((!s_not0f) ? 1 : 2);
}

// -------- packed fp32x2 helpers (sm_100+) ----------------------------------
__device__ __forceinline__ u64 ffma2(u64 a, u64 b, u64 c) {
    u64 d;
    asm("fma.rn.f32x2 %0, %1, %2, %3;" : "=l"(d) : "l"(a), "l"(b), "l"(c));
    return d;
}
__device__ __forceinline__ float2 up2(u64 v) {
    float2 r;
    asm("mov.b64 {%0, %1}, %2;" : "=f"(r.x), "=f"(r.y) : "l"(v));
    return r;
}
__device__ __forceinline__ u64 dup2(float f) {
    u64 r;
    asm("mov.b64 %0, {%1, %1};" : "=l"(r) : "f"(f));
    return r;
}

__device__ __forceinline__ float wredmax(float v) {
    #pragma unroll
    for (int o = 16; o; o >>= 1) v = fmaxf(v, __shfl_xor_sync(0xffffffffu, v, o));
    return v;
}
__device__ __forceinline__ float wredsum(float v) {
    #pragma unroll
    for (int o = 16; o; o >>= 1) v += __shfl_xor_sync(0xffffffffu, v, o);
    return v;
}

// Dynamic smem layout (floats):
//  kT     : 64 * 204  = 13056   (k transposed: kT[d][s])
//  MT     : 64 * 40   = 2560    (folded matrix transposed: MT[d][o])
//  sPart  : 9 * 204   = 1836    (per-o-group score partials)
//  sC     : 40
//  sW2    : 40
//  sQ     : 64
//  sScore : 208
//  sRed   : 32
#define SMEM_FLOATS (64*KTST + 64*MTST + 9*SPST + 40 + 40 + 64 + 208 + 32)

__global__ void __launch_bounds__(256, 2)
twb_kernel(const float* __restrict__ query,
           const float* __restrict__ key,
           const float* __restrict__ W1,
           const float* __restrict__ b1,
           const float* __restrict__ prelu_a,
           const float* __restrict__ W2,
           const float* __restrict__ b2,
           const void*  __restrict__ maskp,
           float* __restrict__ out)
{
    extern __shared__ float smem[];
    float* kT     = smem;                       // [64][KTST]
    float* MT     = kT + 64 * KTST;             // [64][MTST]
    float* sPart  = MT + 64 * MTST;             // [9][SPST]
    float* sC     = sPart + 9 * SPST;           // [40]
    float* sW2    = sC + 40;                    // [40]
    float* sQ     = sW2 + 40;                   // [64]
    float* sScore = sQ + 64;                    // [208]
    float* sRed   = sScore + 208;               // [32]

    const int cta  = blockIdx.x;                // b*NW + w
    const int b    = cta >> 3;                  // NW == 8
    const int tid  = threadIdx.x;
    const int lane = tid & 31;
    const int wid5 = tid >> 5;

    // ---- Phase 0: q row ---------------------------------------------------
    if (tid < H) sQ[tid] = query[b * H + tid];
    __syncthreads();

    // ---- Phase 1: load k (global, row-major) -> kT (smem, transposed) -----
    // i indexes float4 quads: pair = i>>1 (pair of lanes reads 32B of one row)
    {
        const float4* kg = reinterpret_cast<const float4*>(key + (size_t)cta * SEQ * H);
        for (int i = tid; i < SEQ * (H / 4); i += 256) {
            int pair = i >> 1, sub = i & 1;
            int s   = pair % SEQ;
            int c4  = (pair / SEQ) * 2 + sub;       // 0..15
            float4 v = kg[s * (H / 4) + c4];
            int d0 = c4 * 4;
            kT[(d0 + 0) * KTST + s] = v.x;
            kT[(d0 + 1) * KTST + s] = v.y;
            kT[(d0 + 2) * KTST + s] = v.z;
            kT[(d0 + 3) * KTST + s] = v.w;
        }
    }

    // ---- Phase 2: MT[d][o] = W1b - W1c + W1d*q[d] ; sC ; sW2 --------------
    for (int i = tid; i < FF * H; i += 256) {
        int o = i % FF, d = i / FF;
        const float* w1r = W1 + o * (4 * H);
        MT[d * MTST + o] = w1r[64 + d] - w1r[128 + d] + w1r[192 + d] * sQ[d];
    }
    if (tid < FF) {
        const float* w1r = W1 + tid * (4 * H);
        float a0 = b1[tid], a1 = 0.f, a2 = 0.f, a3 = 0.f;
        #pragma unroll 4
        for (int d = 0; d < H; d += 4) {
            a0 = fmaf(w1r[d + 0] + w1r[128 + d + 0], sQ[d + 0], a0);
            a1 = fmaf(w1r[d + 1] + w1r[128 + d + 1], sQ[d + 1], a1);
            a2 = fmaf(w1r[d + 2] + w1r[128 + d + 2], sQ[d + 2], a2);
            a3 = fmaf(w1r[d + 3] + w1r[128 + d + 3], sQ[d + 3], a3);
        }
        sC[tid]  = (a0 + a1) + (a2 + a3);
        sW2[tid] = W2[tid];
    }
    __syncthreads();

    const float pa  = prelu_a[0];
    const float b2v = b2[0];

    // ---- Phase 3: register-tiled GEMM, 8s x 4o per thread ------------------
    // thread t<225: sg = t%25 (s0=sg*8), og = t/25 (o0=og*4)
    if (tid < 225) {
        const int sg = tid % 25, og = tid / 25;
        const int s0 = sg * 8,  o0 = og * 4;

        const char* kb = (const char*)(kT + s0);
        const char* mb = (const char*)(MT + o0);

        u64 acc[4][4];
        #pragma unroll
        for (int i = 0; i < 4; i++)
            #pragma unroll
            for (int j = 0; j < 4; j++) acc[i][j] = 0ull;

        #pragma unroll 4
        for (int d = 0; d < H; d++) {
            const ulonglong2* kq = (const ulonglong2*)kb;
            ulonglong2 kA = kq[0];                       // (s0,s0+1),(s0+2,s0+3)
            ulonglong2 kB = kq[1];                       // (s0+4..s0+7)
            float4 mf = *(const float4*)mb;              // M[d][o0..o0+3]
            kb += KTST * 4;
            mb += MTST * 4;

            u64 kk0 = kA.x, kk1 = kA.y, kk2 = kB.x, kk3 = kB.y;
            u64 m0 = dup2(mf.x), m1 = dup2(mf.y), m2 = dup2(mf.z), m3 = dup2(mf.w);

            acc[0][0] = ffma2(kk0, m0, acc[0][0]);
            acc[1][0] = ffma2(kk1, m0, acc[1][0]);
            acc[2][0] = ffma2(kk2, m0, acc[2][0]);
            acc[3][0] = ffma2(kk3, m0, acc[3][0]);
            acc[0][1] = ffma2(kk0, m1, acc[0][1]);
            acc[1][1] = ffma2(kk1, m1, acc[1][1]);
            acc[2][1] = ffma2(kk2, m1, acc[2][1]);
            acc[3][1] = ffma2(kk3, m1, acc[3][1]);
            acc[0][2] = ffma2(kk0, m2, acc[0][2]);
            acc[1][2] = ffma2(kk1, m2, acc[1][2]);
            acc[2][2] = ffma2(kk2, m2, acc[2][2]);
            acc[3][2] = ffma2(kk3, m2, acc[3][2]);
            acc[0][3] = ffma2(kk0, m3, acc[0][3]);
            acc[1][3] = ffma2(kk1, m3, acc[1][3]);
            acc[2][3] = ffma2(kk2, m3, acc[2][3]);
            acc[3][3] = ffma2(kk3, m3, acc[3][3]);
        }

        // epilogue: h = acc + c ; PReLU ; partial score = sum_o W2[o]*h
        float sp[8];
        #pragma unroll
        for (int i = 0; i < 8; i++) sp[i] = 0.f;
        #pragma unroll
        for (int j = 0; j < 4; j++) {
            int o = o0 + j;
            float c = sC[o], w2 = sW2[o];
            #pragma unroll
            for (int i = 0; i < 4; i++) {
                float2 f = up2(acc[i][j]);
                float h0 = f.x + c; h0 = (h0 >= 0.f) ? h0 : pa * h0;
                float h1 = f.y + c; h1 = (h1 >= 0.f) ? h1 : pa * h1;
                sp[2 * i]     = fmaf(w2, h0, sp[2 * i]);
                sp[2 * i + 1] = fmaf(w2, h1, sp[2 * i + 1]);
            }
        }
        float4* dst = (float4*)(sPart + og * SPST + s0);
        dst[0] = make_float4(sp[0], sp[1], sp[2], sp[3]);
        dst[1] = make_float4(sp[4], sp[5], sp[6], sp[7]);
    }
    __syncthreads();

    // ---- Phase 4: reduce partials, mask, softmax ---------------------------
    float score = -1e30f;
    if (tid < SEQ) {
        float sc = b2v;
        #pragma unroll
        for (int og = 0; og < 9; og++) sc += sPart[og * SPST + tid];

        size_t midx = (size_t)cta * SEQ + tid;
        int mode = g_mask_mode;
        bool masked;
        if (mode == 0)      masked = ((const int*)maskp)[midx] != 0;
        else if (mode == 1) masked = ((const float*)maskp)[midx] != 0.0f;
        else                masked = ((const unsigned char*)maskp)[midx] != 0;
        score = masked ? -10000.0f : sc;
    }

    float wm = wredmax(score);
    if (lane == 0) sRed[wid5] = wm;
    __syncthreads();
    float mx = sRed[0];
    #pragma unroll
    for (int i = 1; i < 8; i++) mx = fmaxf(mx, sRed[i]);
    __syncthreads();                      // before sRed reuse

    float e = (tid < SEQ) ? __expf(score - mx) : 0.0f;
    if (tid < SEQ) sScore[tid] = e;
    float ws = wredsum(e);
    if (lane == 0) sRed[wid5] = ws;
    __syncthreads();                      // also orders sScore writes for phase 5
    float sum = sRed[0];
    #pragma unroll
    for (int i = 1; i < 8; i++) sum += sRed[i];
    float inv = 1.0f / sum;

    // ---- Phase 5: out[d] = inv * sum_s e_s * kT[d][s] ----------------------
    // warp w handles d = w*8 .. w*8+7; lanes stride over s (contiguous kT row)
    #pragma unroll
    for (int rep = 0; rep < 8; rep++) {
        int d = wid5 * 8 + rep;
        const float* kr = kT + d * KTST;
        float a = 0.f;
        #pragma unroll 7
        for (int s = lane; s < SEQ; s += 32)
            a = fmaf(sScore[s], kr[s], a);
        a = wredsum(a);
        if (lane == 0) out[(size_t)cta * H + d] = a * inv;
    }
}

extern "C" void kernel_launch(void* const* d_in, const int* in_sizes, int n_in,
                              void* d_out, int out_size) {
    const float* query = (const float*)d_in[0];
    const float* key   = (const float*)d_in[1];
    const float* W1    = (const float*)d_in[2];
    const float* b1    = (const float*)d_in[3];
    const float* pa    = (const float*)d_in[4];
    const float* W2    = (const float*)d_in[5];
    const float* b2    = (const float*)d_in[6];
    const void*  mask  = d_in[7];
    float* out = (float*)d_out;

    int n_bw = in_sizes[1] / (SEQ * H);    // B*W (= 4096)

    detect_mask_kernel<<<1, 256>>>((const unsigned int*)mask, 4096);

    const int smem_bytes = SMEM_FLOATS * (int)sizeof(float);
    cudaFuncSetAttribute(twb_kernel,
                         cudaFuncAttributeMaxDynamicSharedMemorySize,
                         smem_bytes);
    twb_kernel<<<n_bw, 256, smem_bytes>>>(query, key, W1, b1, pa, W2, b2,
                                          mask, out);
}

// round 15
// speedup vs baseline: 1.6114x; 1.6114x over previous
#include <cuda_runtime.h>
#include <cuda_bf16.h>
#include <cstdint>

// Problem constants (fixed shapes for TimeWindowBlock_3925600108827)
#define H    64      // hidden
#define FF   36      // MLP hidden
#define SEQ  200     // S
#define NW   8       // W windows
#define KPAD 68      // sK row stride (floats): conflict-free column reads in phase 5

typedef unsigned long long u64;

// -------- mask dtype autodetection (bool may arrive as i32 / f32 / u8) ----
__device__ int g_mask_mode;   // 0 = int32, 1 = float32, 2 = byte

__global__ void detect_mask_kernel(const unsigned int* m, int nwords) {
    __shared__ int s_not01, s_not0f;
    if (threadIdx.x == 0) { s_not01 = 0; s_not0f = 0; }
    __syncthreads();
    int n01 = 0, n0f = 0;
    for (int i = threadIdx.x; i < nwords; i += blockDim.x) {
        unsigned int w = m[i];
        if (w > 1u) n01 = 1;
        if (w != 0u && w != 0x3f800000u) n0f = 1;
    }
    if (n01) s_not01 = 1;
    if (n0f) s_not0f = 1;
    __syncthreads();
    if (threadIdx.x == 0)
        g_mask_mode = (!s_not01) ? 0 : ((!s_not0f) ? 1 : 2);
}

// -------- packed fp32x2 helpers (sm_100+) ----------------------------------
__device__ __forceinline__ u64 ffma2(u64 a, u64 b, u64 c) {
    u64 d;
    asm("fma.rn.f32x2 %0, %1, %2, %3;" : "=l"(d) : "l"(a), "l"(b), "l"(c));
    return d;
}
__device__ __forceinline__ float2 up2(u64 v) {
    float2 r;
    asm("mov.b64 {%0, %1}, %2;" : "=f"(r.x), "=f"(r.y) : "l"(v));
    return r;
}

__device__ __forceinline__ float wredmax(float v) {
    #pragma unroll
    for (int o = 16; o; o >>= 1) v = fmaxf(v, __shfl_xor_sync(0xffffffffu, v, o));
    return v;
}
__device__ __forceinline__ float wredsum(float v) {
    #pragma unroll
    for (int o = 16; o; o >>= 1) v += __shfl_xor_sync(0xffffffffu, v, o);
    return v;
}

// Dynamic smem layout (floats):
//  sK     : SEQ*KPAD = 13600   (k row-major, padded)
//  sM     : FF*H     = 2304    (folded matrix, row-major: broadcast reads)
//  sC     : 40
//  sW2    : 40
//  sQ     : 64
//  sScore : 208
//  sRed   : 32
//  sP     : 128                (phase-5 partial combine)
#define SMEM_FLOATS (SEQ*KPAD + FF*H + 40 + 40 + 64 + 208 + 32 + 128)

__global__ void __launch_bounds__(128, 3)
twb_kernel(const float* __restrict__ query,
           const float* __restrict__ key,
           const float* __restrict__ W1,
           const float* __restrict__ b1,
           const float* __restrict__ prelu_a,
           const float* __restrict__ W2,
           const float* __restrict__ b2,
           const void*  __restrict__ maskp,
           float* __restrict__ out)
{
    extern __shared__ float smem[];
    float* sK     = smem;                 // [SEQ][KPAD]
    float* sM     = sK + SEQ * KPAD;      // [FF][H]
    float* sC     = sM + FF * H;          // [40]
    float* sW2    = sC + 40;              // [40]
    float* sQ     = sW2 + 40;             // [64]
    float* sScore = sQ + 64;              // [208]
    float* sRed   = sScore + 208;         // [32]
    float* sP     = sRed + 32;            // [128]

    const int cta  = blockIdx.x;          // b*NW + w
    const int b    = cta >> 3;            // NW == 8
    const int tid  = threadIdx.x;
    const int lane = tid & 31;
    const int wid5 = tid >> 5;

    // ---- Phase 0/1: q row + k tile (row-major, padded) --------------------
    if (tid < H) sQ[tid] = query[b * H + tid];

    {
        const float4* kg = reinterpret_cast<const float4*>(key + (size_t)cta * SEQ * H);
        float4* sK4 = reinterpret_cast<float4*>(sK);
        #pragma unroll 5
        for (int i = tid; i < SEQ * (H / 4); i += 128) {
            int s  = i >> 4;               // 16 float4 per row
            int c4 = i & 15;
            sK4[s * (KPAD / 4) + c4] = kg[i];  // KPAD/4 == 17
        }
    }
    __syncthreads();

    // ---- Phase 2: sM[o][d] = W1b - W1c + W1d*q[d] ; sC ; sW2 --------------
    for (int i = tid; i < FF * H; i += 128) {
        int o = i >> 6, d = i & 63;
        const float* w1r = W1 + o * (4 * H);
        sM[i] = w1r[64 + d] - w1r[128 + d] + w1r[192 + d] * sQ[d];
    }
    if (tid < FF) {
        const float* w1r = W1 + tid * (4 * H);
        float a0 = b1[tid], a1 = 0.f, a2 = 0.f, a3 = 0.f;
        #pragma unroll 4
        for (int d = 0; d < H; d += 4) {
            a0 = fmaf(w1r[d + 0] + w1r[128 + d + 0], sQ[d + 0], a0);
            a1 = fmaf(w1r[d + 1] + w1r[128 + d + 1], sQ[d + 1], a1);
            a2 = fmaf(w1r[d + 2] + w1r[128 + d + 2], sQ[d + 2], a2);
            a3 = fmaf(w1r[d + 3] + w1r[128 + d + 3], sQ[d + 3], a3);
        }
        sC[tid]  = (a0 + a1) + (a2 + a3);
        sW2[tid] = W2[tid];
    }
    __syncthreads();

    const float pa  = prelu_a[0];
    const float b2v = b2[0];

    // ---- Phase 3: thread t<100 handles s0=2t, s0+1 -------------------------
    // M rows are warp-broadcast LDS.128 (1 wavefront each), amortized over
    // TWO k rows held in registers -> M traffic halved vs 1-row/thread.
    if (tid < 100) {
        const int s0 = tid * 2;
        u64 kA[32], kB[32];
        {
            const ulonglong2* r0 = reinterpret_cast<const ulonglong2*>(sK + (s0    ) * KPAD);
            const ulonglong2* r1 = reinterpret_cast<const ulonglong2*>(sK + (s0 + 1) * KPAD);
            #pragma unroll
            for (int j = 0; j < 16; j++) {
                ulonglong2 t0 = r0[j];
                ulonglong2 t1 = r1[j];
                kA[2 * j]     = t0.x;
                kA[2 * j + 1] = t0.y;
                kB[2 * j]     = t1.x;
                kB[2 * j + 1] = t1.y;
            }
        }

        float sc0 = b2v, sc1 = b2v;
        #pragma unroll 2
        for (int o = 0; o < FF; o++) {
            const ulonglong2* mrow = reinterpret_cast<const ulonglong2*>(sM + o * H);
            u64 a00 = 0ull, a01 = 0ull, a10 = 0ull, a11 = 0ull;
            #pragma unroll
            for (int j = 0; j < 16; j++) {
                ulonglong2 m = mrow[j];            // broadcast LDS.128
                a00 = ffma2(m.x, kA[2 * j],     a00);
                a01 = ffma2(m.y, kA[2 * j + 1], a01);
                a10 = ffma2(m.x, kB[2 * j],     a10);
                a11 = ffma2(m.y, kB[2 * j + 1], a11);
            }
            float c = sC[o], w2 = sW2[o];
            float2 f0 = up2(a00), f1 = up2(a01);
            float h0 = (f0.x + f0.y) + (f1.x + f1.y) + c;
            h0 = (h0 >= 0.f) ? h0 : pa * h0;
            sc0 = fmaf(w2, h0, sc0);
            float2 g0 = up2(a10), g1 = up2(a11);
            float h1 = (g0.x + g0.y) + (g1.x + g1.y) + c;
            h1 = (h1 >= 0.f) ? h1 : pa * h1;
            sc1 = fmaf(w2, h1, sc1);
        }

        // mask both rows (True -> -10000)
        size_t midx = (size_t)cta * SEQ + s0;
        int mode = g_mask_mode;
        bool m0, m1;
        if (mode == 0) {
            m0 = ((const int*)maskp)[midx]     != 0;
            m1 = ((const int*)maskp)[midx + 1] != 0;
        } else if (mode == 1) {
            m0 = ((const float*)maskp)[midx]     != 0.0f;
            m1 = ((const float*)maskp)[midx + 1] != 0.0f;
        } else {
            m0 = ((const unsigned char*)maskp)[midx]     != 0;
            m1 = ((const unsigned char*)maskp)[midx + 1] != 0;
        }
        sScore[s0]     = m0 ? -10000.0f : sc0;
        sScore[s0 + 1] = m1 ? -10000.0f : sc1;
    }
    __syncthreads();

    // ---- Phase 4: softmax over SEQ (128 threads, strided by 128) -----------
    float v0 = sScore[tid];
    float v1 = (tid + 128 < SEQ) ? sScore[tid + 128] : -1e30f;
    float loc = fmaxf(v0, v1);
    float wm = wredmax(loc);
    if (lane == 0) sRed[wid5] = wm;
    __syncthreads();
    float mx = fmaxf(fmaxf(sRed[0], sRed[1]), fmaxf(sRed[2], sRed[3]));
    __syncthreads();                       // before sRed reuse

    float e0 = __expf(v0 - mx);
    float e1 = (tid + 128 < SEQ) ? __expf(v1 - mx) : 0.0f;
    sScore[tid] = e0;
    if (tid + 128 < SEQ) sScore[tid + 128] = e1;
    float ws = wredsum(e0 + e1);
    if (lane == 0) sRed[wid5] = ws;
    __syncthreads();                       // orders sScore writes for phase 5
    float sum = (sRed[0] + sRed[1]) + (sRed[2] + sRed[3]);
    float inv = 1.0f / sum;

    // ---- Phase 5: out[d] = inv * sum_s e_s * sK[s][d] ----------------------
    // thread: d = tid&63, g = tid>>6 in {0,1}; s = g, g+2, ... (100 each)
    {
        int d = tid & 63, g = tid >> 6;
        float acc = 0.f;
        #pragma unroll 5
        for (int s = g; s < SEQ; s += 2)
            acc = fmaf(sScore[s], sK[s * KPAD + d], acc);
        sP[tid] = acc;
    }
    __syncthreads();
    if (tid < 64)
        out[(size_t)cta * H + tid] = (sP[tid] + sP[tid + 64]) * inv;
}

extern "C" void kernel_launch(void* const* d_in, const int* in_sizes, int n_in,
                              void* d_out, int out_size) {
    const float* query = (const float*)d_in[0];
    const float* key   = (const float*)d_in[1];
    const float* W1    = (const float*)d_in[2];
    const float* b1    = (const float*)d_in[3];
    const float* pa    = (const float*)d_in[4];
    const float* W2    = (const float*)d_in[5];
    const float* b2    = (const float*)d_in[6];
    const void*  mask  = d_in[7];
    float* out = (float*)d_out;

    int n_bw = in_sizes[1] / (SEQ * H);    // B*W (= 4096)

    detect_mask_kernel<<<1, 256>>>((const unsigned int*)mask, 4096);

    const int smem_bytes = SMEM_FLOATS * (int)sizeof(float);
    cudaFuncSetAttribute(twb_kernel,
                         cudaFuncAttributeMaxDynamicSharedMemorySize,
                         smem_bytes);
    twb_kernel<<<n_bw, 128, smem_bytes>>>(query, key, W1, b1, pa, W2, b2,
                                          mask, out);
}